// round 16
// baseline (speedup 1.0000x reference)
#include <cuda_runtime.h>
#include <math.h>

#define FULL_MASK 0xFFFFFFFFu

constexpr int MAXN  = 65536;
constexpr int HID   = 32;
constexpr int MAXB  = 64;
constexpr int HCAP  = 18432;      // per HALF-graph compact edge capacity
constexpr int HCAPP = 36864;      // per HALF-graph PADDED capacity
constexpr int CHUNK = 4096;       // edges per k_group CTA
constexpr int ZROW  = 1024;       // sentinel node id -> zero row in SG

// ---- scratch (device symbols; ONLY accessed from device code) ----
__device__ int            g_gcnt[2 * MAXB];
__device__ unsigned       g_grp[2 * MAXB * HCAP];      // packed (dl<<16 | sl)
__device__ unsigned short g_srt[2 * MAXB * HCAPP];     // dst-sorted, PADDED
__device__ int            g_start[MAXN];
__device__ int            g_deg[MAXN];                 // padded length (mult of 32)
__device__ float          g_dis[MAXN];
__device__ float          g_bufA[MAXN * HID];          // g1 (unscaled)
__device__ float          g_bufB[MAXN * HID];          // g2 (unscaled)
__device__ float          g_pooled2[2 * MAXB * HID];

// smem byte offsets for conv kernels (SG has 1025 rows: 1024 + zero row)
constexpr int SGB    = (1024 * HID + 32) * 4;          // 131200
constexpr int ODIS   = SGB;                            // [1024] f32
constexpr int OSTART = ODIS + 4096;                    // [512] i32
constexpr int ODEG   = OSTART + 2048;                  // [512] i32
constexpr int OWT    = ODEG + 2048;                    // [32*33] f32
constexpr int OPOOL  = OWT + 4224;                     // [1024] f32 (conv2)

// ---------------------------------------------------------------------------
__global__ void __launch_bounds__(128) k_init0() {
    g_gcnt[threadIdx.x] = 0;
}

// ---------------------------------------------------------------------------
// bin edges by (graph, dst-half): 128 bins, smem rank atomics
__global__ void __launch_bounds__(512) k_group(const int* __restrict__ src,
                                               const int* __restrict__ dst,
                                               int e, int shift) {
    __shared__ int sh_cnt[128];
    __shared__ int sh_base[128];
    int tid = threadIdx.x;
    if (tid < 128) sh_cnt[tid] = 0;
    __syncthreads();

    const int ml = (1 << shift) - 1;
    int base = blockIdx.x * CHUNK;
    int      mybin[8];
    int      myrank[8];
    unsigned mypk[8];

    int t8 = base + tid * 8;
    if (t8 + 7 < e) {
        const int4* s4 = (const int4*)(src + t8);
        const int4* d4 = (const int4*)(dst + t8);
        int4 sa = s4[0], sb = s4[1];
        int4 da = d4[0], db = d4[1];
        int ss[8] = {sa.x, sa.y, sa.z, sa.w, sb.x, sb.y, sb.z, sb.w};
        int dd[8] = {da.x, da.y, da.z, da.w, db.x, db.y, db.z, db.w};
        #pragma unroll
        for (int j = 0; j < 8; j++) {
            int b = dd[j] >> (shift - 1);
            mybin[j]  = b;
            mypk[j]   = ((unsigned)(dd[j] & ml) << 16) | (unsigned)(ss[j] & ml);
            myrank[j] = atomicAdd(&sh_cnt[b], 1);
        }
    } else {
        #pragma unroll
        for (int j = 0; j < 8; j++) {
            int i = t8 + j;
            if (i < e) {
                int s = src[i], d = dst[i];
                int b = d >> (shift - 1);
                mybin[j]  = b;
                mypk[j]   = ((unsigned)(d & ml) << 16) | (unsigned)(s & ml);
                myrank[j] = atomicAdd(&sh_cnt[b], 1);
            } else mybin[j] = -1;
        }
    }
    __syncthreads();
    if (tid < 128) {
        int c = sh_cnt[tid];
        sh_base[tid] = c ? atomicAdd(&g_gcnt[tid], c) : 0;
    }
    __syncthreads();
    #pragma unroll
    for (int j = 0; j < 8; j++) {
        int b = mybin[j];
        if (b >= 0) {
            int idx = sh_base[b] + myrank[j];
            if (idx < HCAP)
                g_grp[b * HCAP + idx] = mypk[j];
        }
    }
}

// ---------------------------------------------------------------------------
// counting sort per half-graph with PADDING to 32-multiples (+ fused GEMM1)
__global__ void __launch_bounds__(512) k_sort(const float* __restrict__ x,
                                              const float* __restrict__ W1,
                                              int shift) {
    extern __shared__ char sm[];
    int*            HIST = (int*)sm;                              // [512]
    int*            WS   = (int*)(sm + 2048);                     // [16]
    int*            TOT  = (int*)(sm + 2048 + 60);                // [1]
    unsigned short* RANK = (unsigned short*)(sm + 2048 + 64);     // [HCAP]
    unsigned short* SRT  = (unsigned short*)(sm + 2048 + 64 + 2 * HCAP);  // [HCAPP]
    float*          Wt   = (float*)(sm + 2048 + 64 + 2 * HCAP + 2 * HCAPP);

    const int h   = blockIdx.x;
    const int tid = threadIdx.x;
    const int lane = tid & 31, wid = tid >> 5;
    int cnt = g_gcnt[h];
    if (cnt > HCAP) cnt = HCAP;
    const unsigned* __restrict__ grp = &g_grp[h * HCAP];
    const int node0 = ((h >> 1) << shift) + ((h & 1) << (shift - 1));

    HIST[tid] = 0;
    {
        int o = tid >> 4, k = tid & 15;
        Wt[k * 33 + o] = W1[tid];
    }
    __syncthreads();
    for (int i = tid; i < cnt; i += 512) {
        unsigned pk = grp[i];
        RANK[i] = (unsigned short)atomicAdd(&HIST[(pk >> 16) & 511], 1);
    }
    __syncthreads();
    int c = HIST[tid];
    int plen = (c + 31) & ~31;
    int v = plen;
    #pragma unroll
    for (int o = 1; o < 32; o <<= 1) {
        int u = __shfl_up_sync(FULL_MASK, v, o);
        if (lane >= o) v += u;
    }
    if (lane == 31) WS[wid] = v;
    __syncthreads();
    if (wid == 0 && lane < 16) {
        int s = WS[lane];
        #pragma unroll
        for (int o = 1; o < 16; o <<= 1) {
            int u = __shfl_up_sync(0xFFFFu, s, o);
            if (lane >= o) s += u;
        }
        WS[lane] = s;
    }
    __syncthreads();
    int excl = v - plen + (wid ? WS[wid - 1] : 0);
    if (excl > HCAPP) excl = HCAPP;
    if (excl + plen > HCAPP) plen = (HCAPP - excl) & ~31;
    HIST[tid] = excl;
    g_start[node0 + tid] = excl;
    g_deg[node0 + tid]   = plen;
    g_dis[node0 + tid]   = rsqrtf((float)(c + 1));
    if (tid == 511) TOT[0] = excl + plen;
    __syncthreads();
    int ptot = TOT[0];
    {
        unsigned fill = ((unsigned)ZROW << 16) | (unsigned)ZROW;
        int nw = (ptot + 1) >> 1;
        unsigned* sw = (unsigned*)SRT;
        for (int i = tid; i < nw; i += 512) sw[i] = fill;
    }
    __syncthreads();
    for (int i = tid; i < cnt; i += 512) {
        unsigned pk = grp[i];
        int pos = HIST[(pk >> 16) & 511] + (int)RANK[i];
        if (pos < HCAPP) SRT[pos] = (unsigned short)(pk & 0xFFFFu);
    }
    __syncthreads();
    {
        int nwords = (ptot + 1) >> 1;
        unsigned* dstw = (unsigned*)g_srt + h * (HCAPP >> 1);
        const unsigned* srcw = (const unsigned*)SRT;
        for (int i = tid; i < nwords; i += 512)
            dstw[i] = srcw[i];
    }

    // ---- fused GEMM1: g_bufA[node] = x @ W1^T for this CTA's 512 nodes ----
    float w[16];
    #pragma unroll
    for (int k = 0; k < 16; k++) w[k] = Wt[k * 33 + lane];
    #pragma unroll 2
    for (int it = 0; it < 32; it++) {
        int node = node0 + wid * 32 + it;
        float xv = (lane < 16) ? x[(size_t)node * 16 + lane] : 0.f;
        float a0 = 0.f, a1 = 0.f;
        #pragma unroll
        for (int k = 0; k < 16; k += 2) {
            a0 += __shfl_sync(FULL_MASK, xv, k)     * w[k];
            a1 += __shfl_sync(FULL_MASK, xv, k + 1) * w[k + 1];
        }
        g_bufA[(size_t)node * HID + lane] = a0 + a1;
    }
}

// ---------------------------------------------------------------------------
// conv1: copy g_bufA*dis to smem (+zero row), padded prefetched gather,
// tanh, fused GEMM2 (weights read from SMEM, not register array) -> g_bufB
__global__ void __launch_bounds__(1024, 1) k_conv1(const float* __restrict__ b1,
                                                   const float* __restrict__ W2,
                                                   int shift) {
    extern __shared__ char sm[];
    float*  SG     = (float*)sm;
    float*  DISF   = (float*)(sm + ODIS);
    int*    STARTs = (int*)(sm + OSTART);
    int*    DEGs   = (int*)(sm + ODEG);
    float*  W2t    = (float*)(sm + OWT);

    const int h     = blockIdx.x;
    const int half  = h & 1;
    const int gbase = (h >> 1) << shift;
    const int tid   = threadIdx.x;
    const int lane  = tid & 31;
    const int wid   = tid >> 5;
    const int c8    = lane & 7;
    const int grp4  = lane >> 3;
    const int node0 = gbase + (half << (shift - 1));

    DISF[tid] = g_dis[gbase + tid];
    if (tid < 512) {
        STARTs[tid] = g_start[node0 + tid];
        DEGs[tid]   = g_deg[node0 + tid];
    }
    {
        int r = tid >> 5, cc = tid & 31;
        W2t[cc * 33 + r] = W2[tid];
    }
    __syncthreads();
    {
        float4* SG4w = (float4*)SG;
        const float4* G4 = (const float4*)(g_bufA + (size_t)gbase * HID);
        #pragma unroll
        for (int i = 0; i < 8; i++) {
            int idx = tid + i * 1024;
            float4 vv = G4[idx];
            float d = DISF[idx >> 3];
            vv.x *= d; vv.y *= d; vv.z *= d; vv.w *= d;
            SG4w[idx] = vv;
        }
        if (tid < 32) SG[ZROW * HID + tid] = 0.f;
    }
    __syncthreads();

    float4 b1v = ((const float4*)b1)[c8];
    const float* W2l = W2t + lane;             // column for this lane
    const unsigned short* __restrict__ srtb = g_srt + (size_t)h * HCAPP;
    for (int it = 0; it < 16; it++) {
        int ndl = wid * 16 + it;
        int ndg = (half << (shift - 1)) + ndl;
        int st = STARTs[ndl], m = DEGs[ndl];
        const unsigned short* srtp = srtb + st;
        unsigned long long acc01 = 0ull, acc23 = 0ull;
        if (grp4 == 0) {
            ulonglong2 s0 = *(const ulonglong2*)(SG + ndg * HID + (c8 << 2));
            acc01 = s0.x; acc23 = s0.y;
        }
        if (m > 0) {
            int sv = srtp[lane];
            for (int p = 0; p < m; ) {
                int svc = sv;
                p += 32;
                if (p < m) sv = srtp[p + lane];
                #pragma unroll
                for (int i = 0; i < 8; i++) {
                    int s = __shfl_sync(FULL_MASK, svc, i * 4 + grp4);
                    ulonglong2 gg = *(const ulonglong2*)(SG + s * HID + (c8 << 2));
                    asm("add.rn.f32x2 %0, %0, %1;" : "+l"(acc01) : "l"(gg.x));
                    asm("add.rn.f32x2 %0, %0, %1;" : "+l"(acc23) : "l"(gg.y));
                }
            }
        }
        float ax = __uint_as_float((unsigned)acc01);
        float ay = __uint_as_float((unsigned)(acc01 >> 32));
        float az = __uint_as_float((unsigned)acc23);
        float aw = __uint_as_float((unsigned)(acc23 >> 32));
        ax += __shfl_xor_sync(FULL_MASK, ax, 8);
        ay += __shfl_xor_sync(FULL_MASK, ay, 8);
        az += __shfl_xor_sync(FULL_MASK, az, 8);
        aw += __shfl_xor_sync(FULL_MASK, aw, 8);
        ax += __shfl_xor_sync(FULL_MASK, ax, 16);
        ay += __shfl_xor_sync(FULL_MASK, ay, 16);
        az += __shfl_xor_sync(FULL_MASK, az, 16);
        aw += __shfl_xor_sync(FULL_MASK, aw, 16);
        float h2a[4] = {0.f, 0.f, 0.f, 0.f};
        if (grp4 == 0) {
            float d = DISF[ndg];
            h2a[0] = tanhf(fmaf(d, ax, b1v.x));
            h2a[1] = tanhf(fmaf(d, ay, b1v.y));
            h2a[2] = tanhf(fmaf(d, az, b1v.z));
            h2a[3] = tanhf(fmaf(d, aw, b1v.w));
        }
        float a0 = 0.f, a1 = 0.f;
        #pragma unroll
        for (int cc = 0; cc < 8; cc++) {
            a0 += __shfl_sync(FULL_MASK, h2a[0], cc) * W2l[(cc * 4 + 0) * 33];
            a1 += __shfl_sync(FULL_MASK, h2a[1], cc) * W2l[(cc * 4 + 1) * 33];
            a0 += __shfl_sync(FULL_MASK, h2a[2], cc) * W2l[(cc * 4 + 2) * 33];
            a1 += __shfl_sync(FULL_MASK, h2a[3], cc) * W2l[(cc * 4 + 3) * 33];
        }
        g_bufB[(size_t)(gbase + ndg) * HID + lane] = a0 + a1;
    }
}

// ---------------------------------------------------------------------------
// conv2: copy g_bufB*dis to smem (+zero row), gather, node linear (weights
// from SMEM) + pool
__global__ void __launch_bounds__(1024, 1) k_conv2(const float* __restrict__ b2,
                                                   const float* __restrict__ Wl,
                                                   const float* __restrict__ bl,
                                                   int shift) {
    extern __shared__ char sm[];
    float*  SG     = (float*)sm;
    float*  DISF   = (float*)(sm + ODIS);
    int*    STARTs = (int*)(sm + OSTART);
    int*    DEGs   = (int*)(sm + ODEG);
    float*  Wlt    = (float*)(sm + OWT);
    float*  POOL   = (float*)(sm + OPOOL);

    const int h     = blockIdx.x;
    const int half  = h & 1;
    const int gbase = (h >> 1) << shift;
    const int tid   = threadIdx.x;
    const int lane  = tid & 31;
    const int wid   = tid >> 5;
    const int c8    = lane & 7;
    const int grp4  = lane >> 3;
    const int node0 = gbase + (half << (shift - 1));

    DISF[tid] = g_dis[gbase + tid];
    if (tid < 512) {
        STARTs[tid] = g_start[node0 + tid];
        DEGs[tid]   = g_deg[node0 + tid];
    }
    {
        int r = tid >> 5, cc = tid & 31;
        Wlt[cc * 33 + r] = Wl[tid];
    }
    __syncthreads();
    {
        float4* SG4w = (float4*)SG;
        const float4* G4 = (const float4*)(g_bufB + (size_t)gbase * HID);
        #pragma unroll
        for (int i = 0; i < 8; i++) {
            int idx = tid + i * 1024;
            float4 vv = G4[idx];
            float d = DISF[idx >> 3];
            vv.x *= d; vv.y *= d; vv.z *= d; vv.w *= d;
            SG4w[idx] = vv;
        }
        if (tid < 32) SG[ZROW * HID + tid] = 0.f;
    }
    __syncthreads();

    float4 b2v = ((const float4*)b2)[c8];
    const float* Wll = Wlt + lane;
    float bll = bl[lane];
    float pacc = 0.f;
    const unsigned short* __restrict__ srtb = g_srt + (size_t)h * HCAPP;
    for (int it = 0; it < 16; it++) {
        int ndl = wid * 16 + it;
        int ndg = (half << (shift - 1)) + ndl;
        int st = STARTs[ndl], m = DEGs[ndl];
        const unsigned short* srtp = srtb + st;
        unsigned long long acc01 = 0ull, acc23 = 0ull;
        if (grp4 == 0) {
            ulonglong2 s0 = *(const ulonglong2*)(SG + ndg * HID + (c8 << 2));
            acc01 = s0.x; acc23 = s0.y;
        }
        if (m > 0) {
            int sv = srtp[lane];
            for (int p = 0; p < m; ) {
                int svc = sv;
                p += 32;
                if (p < m) sv = srtp[p + lane];
                #pragma unroll
                for (int i = 0; i < 8; i++) {
                    int s = __shfl_sync(FULL_MASK, svc, i * 4 + grp4);
                    ulonglong2 gg = *(const ulonglong2*)(SG + s * HID + (c8 << 2));
                    asm("add.rn.f32x2 %0, %0, %1;" : "+l"(acc01) : "l"(gg.x));
                    asm("add.rn.f32x2 %0, %0, %1;" : "+l"(acc23) : "l"(gg.y));
                }
            }
        }
        float ax = __uint_as_float((unsigned)acc01);
        float ay = __uint_as_float((unsigned)(acc01 >> 32));
        float az = __uint_as_float((unsigned)acc23);
        float aw = __uint_as_float((unsigned)(acc23 >> 32));
        ax += __shfl_xor_sync(FULL_MASK, ax, 8);
        ay += __shfl_xor_sync(FULL_MASK, ay, 8);
        az += __shfl_xor_sync(FULL_MASK, az, 8);
        aw += __shfl_xor_sync(FULL_MASK, aw, 8);
        ax += __shfl_xor_sync(FULL_MASK, ax, 16);
        ay += __shfl_xor_sync(FULL_MASK, ay, 16);
        az += __shfl_xor_sync(FULL_MASK, az, 16);
        aw += __shfl_xor_sync(FULL_MASK, aw, 16);
        float h2a[4] = {0.f, 0.f, 0.f, 0.f};
        if (grp4 == 0) {
            float d = DISF[ndg];
            h2a[0] = tanhf(fmaf(d, ax, b2v.x));
            h2a[1] = tanhf(fmaf(d, ay, b2v.y));
            h2a[2] = tanhf(fmaf(d, az, b2v.z));
            h2a[3] = tanhf(fmaf(d, aw, b2v.w));
        }
        float a0 = bll, a1 = 0.f;
        #pragma unroll
        for (int cc = 0; cc < 8; cc++) {
            a0 += __shfl_sync(FULL_MASK, h2a[0], cc) * Wll[(cc * 4 + 0) * 33];
            a1 += __shfl_sync(FULL_MASK, h2a[1], cc) * Wll[(cc * 4 + 1) * 33];
            a0 += __shfl_sync(FULL_MASK, h2a[2], cc) * Wll[(cc * 4 + 2) * 33];
            a1 += __shfl_sync(FULL_MASK, h2a[3], cc) * Wll[(cc * 4 + 3) * 33];
        }
        pacc += tanhf(a0 + a1);
    }
    POOL[wid * 32 + lane] = pacc;
    __syncthreads();
    if (wid == 0) {
        float s = 0.f;
        #pragma unroll
        for (int w = 0; w < 32; w++) s += POOL[w * 32 + lane];
        g_pooled2[h * HID + lane] = s;
    }
}

// ---------------------------------------------------------------------------
__global__ void __launch_bounds__(1024) k_head(const float* __restrict__ share,
                        const float* __restrict__ Wp,  const float* __restrict__ bp,
                        const float* __restrict__ Vw1, const float* __restrict__ Vb1,
                        const float* __restrict__ Vw2, const float* __restrict__ Vb2,
                        const float* __restrict__ Vw3, const float* __restrict__ Vb3,
                        const float* __restrict__ Cw1, const float* __restrict__ Cb1,
                        const float* __restrict__ Cw2, const float* __restrict__ Cb2,
                        float* __restrict__ out, int nb) {
    __shared__ float Wpt[32 * 33], Vw1t[64 * 33], Vw2t[32 * 33],
                     Vw3t[32 * 33], Cw1t[64 * 33];
    int tid = threadIdx.x;
    int lane = tid & 31, wid = tid >> 5;
    {
        int r = tid >> 5, c = tid & 31;
        Wpt[c * 33 + r]  = Wp[tid];
        Vw2t[c * 33 + r] = Vw2[tid];
        Vw3t[c * 33 + r] = Vw3[tid];
    }
    for (int t = tid; t < 2048; t += 1024) {
        int r = t >> 6, c = t & 63;
        Vw1t[c * 33 + r] = Vw1[t];
        Cw1t[c * 33 + r] = Cw1[t];
    }
    __syncthreads();

    int b = blockIdx.x * 32 + wid;
    if (b >= nb) return;
    float pv = g_pooled2[(2 * b) * HID + lane] + g_pooled2[(2 * b + 1) * HID + lane];
    float h1 = bp[lane];
    #pragma unroll
    for (int k = 0; k < 32; k++) h1 += __shfl_sync(FULL_MASK, pv, k) * Wpt[k * 33 + lane];
    float s0 = share[b * 64 + lane];
    float s1 = share[b * 64 + 32 + lane];
    float t = Vb1[lane];
    #pragma unroll
    for (int k = 0; k < 32; k++) t += __shfl_sync(FULL_MASK, s0, k) * Vw1t[k * 33 + lane];
    #pragma unroll
    for (int k = 0; k < 32; k++) t += __shfl_sync(FULL_MASK, s1, k) * Vw1t[(k + 32) * 33 + lane];
    t = tanhf(t);
    float t2 = Vb2[lane];
    #pragma unroll
    for (int k = 0; k < 32; k++) t2 += __shfl_sync(FULL_MASK, t, k) * Vw2t[k * 33 + lane];
    t2 = tanhf(t2);
    float t3 = Vb3[lane];
    #pragma unroll
    for (int k = 0; k < 32; k++) t3 += __shfl_sync(FULL_MASK, t2, k) * Vw3t[k * 33 + lane];
    float z = Cb1[lane];
    #pragma unroll
    for (int k = 0; k < 32; k++) z += __shfl_sync(FULL_MASK, h1, k) * Cw1t[k * 33 + lane];
    #pragma unroll
    for (int k = 0; k < 32; k++) z += __shfl_sync(FULL_MASK, t3, k) * Cw1t[(k + 32) * 33 + lane];
    z = tanhf(z);
    float p = z * Cw2[lane];
    #pragma unroll
    for (int o = 16; o > 0; o >>= 1) p += __shfl_down_sync(FULL_MASK, p, o);
    if (lane == 0) out[b] = p + Cb2[0];
}

// ---------------------------------------------------------------------------
extern "C" void kernel_launch(void* const* d_in, const int* in_sizes, int n_in,
                              void* d_out, int out_size) {
    const float* x      = (const float*)d_in[0];
    const int*   edge   = (const int*)  d_in[1];
    const float* share  = (const float*)d_in[3];
    const float* W1 = (const float*)d_in[4];   const float* b1 = (const float*)d_in[5];
    const float* W2 = (const float*)d_in[6];   const float* b2 = (const float*)d_in[7];
    const float* Wl = (const float*)d_in[8];   const float* bl = (const float*)d_in[9];
    const float* Wp = (const float*)d_in[10];  const float* bp = (const float*)d_in[11];
    const float* Vw1 = (const float*)d_in[12]; const float* Vb1 = (const float*)d_in[13];
    const float* Vw2 = (const float*)d_in[14]; const float* Vb2 = (const float*)d_in[15];
    const float* Vw3 = (const float*)d_in[16]; const float* Vb3 = (const float*)d_in[17];
    const float* Cw1 = (const float*)d_in[18]; const float* Cb1 = (const float*)d_in[19];
    const float* Cw2 = (const float*)d_in[20]; const float* Cb2 = (const float*)d_in[21];

    const int n  = in_sizes[0] / 16;
    const int e  = in_sizes[1] / 2;
    const int nb = in_sizes[3] / 64;
    const int* src = edge;
    const int* dst = edge + e;
    float* out = (float*)d_out;

    int pp = n / nb;                     // 1024
    int shift = 0;
    while ((1 << shift) < pp) shift++;
    const int nh = nb * 2;

    const int SM_SORT  = 2048 + 64 + 2 * HCAP + 2 * HCAPP + 16 * 33 * 4;
    const int SM_CONV1 = OWT + 4224;
    const int SM_CONV2 = OPOOL + 4096;
    static int smem_set = 0;
    if (!smem_set) {
        cudaFuncSetAttribute(k_sort,  cudaFuncAttributeMaxDynamicSharedMemorySize, SM_SORT);
        cudaFuncSetAttribute(k_conv1, cudaFuncAttributeMaxDynamicSharedMemorySize, SM_CONV1);
        cudaFuncSetAttribute(k_conv2, cudaFuncAttributeMaxDynamicSharedMemorySize, SM_CONV2);
        smem_set = 1;
    }

    k_init0<<<1, 128>>>();
    k_group<<<(e + CHUNK - 1) / CHUNK, 512>>>(src, dst, e, shift);
    k_sort<<<nh, 512, SM_SORT>>>(x, W1, shift);              // + fused GEMM1 -> g_bufA
    k_conv1<<<nh, 1024, SM_CONV1>>>(b1, W2, shift);          // agg1 + fused GEMM2 -> g_bufB
    k_conv2<<<nh, 1024, SM_CONV2>>>(b2, Wl, bl, shift);      // agg2 + Wl + pool
    k_head<<<(nb + 31) / 32, 1024>>>(share, Wp, bp, Vw1, Vb1, Vw2, Vb2, Vw3, Vb3,
                                     Cw1, Cb1, Cw2, Cb2, out, nb);
}

// round 17
// speedup vs baseline: 1.1779x; 1.1779x over previous
#include <cuda_runtime.h>
#include <math.h>

#define FULL_MASK 0xFFFFFFFFu

constexpr int MAXN  = 65536;
constexpr int HID   = 32;
constexpr int MAXB  = 64;
constexpr int HCAP  = 18432;
constexpr int HCAPP = 36864;
constexpr int CHUNK = 4096;
constexpr int ZROW  = 1024;

// ---- scratch ----
__device__ int            g_gcnt[2 * MAXB];
__device__ unsigned       g_grp[2 * MAXB * HCAP];
__device__ unsigned short g_srt[2 * MAXB * HCAPP];   // PADDED + chunk-interleaved
__device__ int            g_start[MAXN];
__device__ int            g_deg[MAXN];
__device__ float          g_dis[MAXN];
__device__ float          g_bufA[MAXN * HID];
__device__ float          g_bufB[MAXN * HID];
__device__ float          g_pooled2[2 * MAXB * HID];

// smem offsets (SG = 1025 rows x 32 f32)
constexpr int SGB    = (1024 * HID + 32) * 4;          // 131200
constexpr int ODIS   = SGB;
constexpr int OSTART = ODIS + 4096;
constexpr int ODEG   = OSTART + 2048;
constexpr int OWT    = ODEG + 2048;                    // [32*33] f32
constexpr int OHROW  = OWT + 4224;                     // [32*32] f32 per-warp h rows
constexpr int OPOOL  = OHROW + 4096;                   // [1024] f32 (conv2)

// ---------------------------------------------------------------------------
__global__ void __launch_bounds__(128) k_init0() {
    g_gcnt[threadIdx.x] = 0;
}

// ---------------------------------------------------------------------------
__global__ void __launch_bounds__(512) k_group(const int* __restrict__ src,
                                               const int* __restrict__ dst,
                                               int e, int shift) {
    __shared__ int sh_cnt[128];
    __shared__ int sh_base[128];
    int tid = threadIdx.x;
    if (tid < 128) sh_cnt[tid] = 0;
    __syncthreads();

    const int ml = (1 << shift) - 1;
    int base = blockIdx.x * CHUNK;
    int      mybin[8];
    int      myrank[8];
    unsigned mypk[8];

    int t8 = base + tid * 8;
    if (t8 + 7 < e) {
        const int4* s4 = (const int4*)(src + t8);
        const int4* d4 = (const int4*)(dst + t8);
        int4 sa = s4[0], sb = s4[1];
        int4 da = d4[0], db = d4[1];
        int ss[8] = {sa.x, sa.y, sa.z, sa.w, sb.x, sb.y, sb.z, sb.w};
        int dd[8] = {da.x, da.y, da.z, da.w, db.x, db.y, db.z, db.w};
        #pragma unroll
        for (int j = 0; j < 8; j++) {
            int b = dd[j] >> (shift - 1);
            mybin[j]  = b;
            mypk[j]   = ((unsigned)(dd[j] & ml) << 16) | (unsigned)(ss[j] & ml);
            myrank[j] = atomicAdd(&sh_cnt[b], 1);
        }
    } else {
        #pragma unroll
        for (int j = 0; j < 8; j++) {
            int i = t8 + j;
            if (i < e) {
                int s = src[i], d = dst[i];
                int b = d >> (shift - 1);
                mybin[j]  = b;
                mypk[j]   = ((unsigned)(d & ml) << 16) | (unsigned)(s & ml);
                myrank[j] = atomicAdd(&sh_cnt[b], 1);
            } else mybin[j] = -1;
        }
    }
    __syncthreads();
    if (tid < 128) {
        int c = sh_cnt[tid];
        sh_base[tid] = c ? atomicAdd(&g_gcnt[tid], c) : 0;
    }
    __syncthreads();
    #pragma unroll
    for (int j = 0; j < 8; j++) {
        int b = mybin[j];
        if (b >= 0) {
            int idx = sh_base[b] + myrank[j];
            if (idx < HCAP)
                g_grp[b * HCAP + idx] = mypk[j];
        }
    }
}

// ---------------------------------------------------------------------------
// counting sort with PADDING + chunk interleave (+ fused GEMM1)
// position pos -> slot (pos & ~31) | ((pos & 3) << 3) | ((pos >> 2) & 7),
// so lane-group g's 8 edge ids of each 32-chunk are contiguous (one LDG.128).
__global__ void __launch_bounds__(512) k_sort(const float* __restrict__ x,
                                              const float* __restrict__ W1,
                                              int shift) {
    extern __shared__ char sm[];
    int*            HIST = (int*)sm;
    int*            WS   = (int*)(sm + 2048);
    int*            TOT  = (int*)(sm + 2048 + 60);
    unsigned short* RANK = (unsigned short*)(sm + 2048 + 64);
    unsigned short* SRT  = (unsigned short*)(sm + 2048 + 64 + 2 * HCAP);
    float*          Wt   = (float*)(sm + 2048 + 64 + 2 * HCAP + 2 * HCAPP);

    const int h   = blockIdx.x;
    const int tid = threadIdx.x;
    const int lane = tid & 31, wid = tid >> 5;
    int cnt = g_gcnt[h];
    if (cnt > HCAP) cnt = HCAP;
    const unsigned* __restrict__ grp = &g_grp[h * HCAP];
    const int node0 = ((h >> 1) << shift) + ((h & 1) << (shift - 1));

    HIST[tid] = 0;
    {
        int o = tid >> 4, k = tid & 15;
        Wt[k * 33 + o] = W1[tid];
    }
    __syncthreads();
    for (int i = tid; i < cnt; i += 512) {
        unsigned pk = grp[i];
        RANK[i] = (unsigned short)atomicAdd(&HIST[(pk >> 16) & 511], 1);
    }
    __syncthreads();
    int c = HIST[tid];
    int plen = (c + 31) & ~31;
    int v = plen;
    #pragma unroll
    for (int o = 1; o < 32; o <<= 1) {
        int u = __shfl_up_sync(FULL_MASK, v, o);
        if (lane >= o) v += u;
    }
    if (lane == 31) WS[wid] = v;
    __syncthreads();
    if (wid == 0 && lane < 16) {
        int s = WS[lane];
        #pragma unroll
        for (int o = 1; o < 16; o <<= 1) {
            int u = __shfl_up_sync(0xFFFFu, s, o);
            if (lane >= o) s += u;
        }
        WS[lane] = s;
    }
    __syncthreads();
    int excl = v - plen + (wid ? WS[wid - 1] : 0);
    if (excl > HCAPP) excl = HCAPP;
    if (excl + plen > HCAPP) plen = (HCAPP - excl) & ~31;
    HIST[tid] = excl;
    g_start[node0 + tid] = excl;
    g_deg[node0 + tid]   = plen;
    g_dis[node0 + tid]   = rsqrtf((float)(c + 1));
    if (tid == 511) TOT[0] = excl + plen;
    __syncthreads();
    int ptot = TOT[0];
    {
        unsigned fill = ((unsigned)ZROW << 16) | (unsigned)ZROW;
        int nw = (ptot + 1) >> 1;
        unsigned* sw = (unsigned*)SRT;
        for (int i = tid; i < nw; i += 512) sw[i] = fill;
    }
    __syncthreads();
    for (int i = tid; i < cnt; i += 512) {
        unsigned pk = grp[i];
        int pos = HIST[(pk >> 16) & 511] + (int)RANK[i];
        if (pos < HCAPP) {
            int slot = (pos & ~31) | ((pos & 3) << 3) | ((pos >> 2) & 7);
            SRT[slot] = (unsigned short)(pk & 0xFFFFu);
        }
    }
    __syncthreads();
    {
        int nwords = (ptot + 1) >> 1;
        unsigned* dstw = (unsigned*)g_srt + h * (HCAPP >> 1);
        const unsigned* srcw = (const unsigned*)SRT;
        for (int i = tid; i < nwords; i += 512)
            dstw[i] = srcw[i];
    }

    // fused GEMM1
    float w[16];
    #pragma unroll
    for (int k = 0; k < 16; k++) w[k] = Wt[k * 33 + lane];
    #pragma unroll 2
    for (int it = 0; it < 32; it++) {
        int node = node0 + wid * 32 + it;
        float xv = (lane < 16) ? x[(size_t)node * 16 + lane] : 0.f;
        float a0 = 0.f, a1 = 0.f;
        #pragma unroll
        for (int k = 0; k < 16; k += 2) {
            a0 += __shfl_sync(FULL_MASK, xv, k)     * w[k];
            a1 += __shfl_sync(FULL_MASK, xv, k + 1) * w[k + 1];
        }
        g_bufA[(size_t)node * HID + lane] = a0 + a1;
    }
}

// ---------------------------------------------------------------------------
// conv1: gather (LDG.128 own-index, no index shuffles) + tanh +
// GEMM2 via smem h-row broadcast (no epilogue shuffles) -> g_bufB
__global__ void __launch_bounds__(1024, 1) k_conv1(const float* __restrict__ b1,
                                                   const float* __restrict__ W2,
                                                   int shift) {
    extern __shared__ char sm[];
    float*  SG     = (float*)sm;
    float*  DISF   = (float*)(sm + ODIS);
    int*    STARTs = (int*)(sm + OSTART);
    int*    DEGs   = (int*)(sm + ODEG);
    float*  W2t    = (float*)(sm + OWT);
    float*  HROW   = (float*)(sm + OHROW);

    const int h     = blockIdx.x;
    const int half  = h & 1;
    const int gbase = (h >> 1) << shift;
    const int tid   = threadIdx.x;
    const int lane  = tid & 31;
    const int wid   = tid >> 5;
    const int c8    = lane & 7;
    const int grp4  = lane >> 3;
    const int node0 = gbase + (half << (shift - 1));

    DISF[tid] = g_dis[gbase + tid];
    if (tid < 512) {
        STARTs[tid] = g_start[node0 + tid];
        DEGs[tid]   = g_deg[node0 + tid];
    }
    {
        int r = tid >> 5, cc = tid & 31;
        W2t[cc * 33 + r] = W2[tid];
    }
    __syncthreads();
    {
        float4* SG4w = (float4*)SG;
        const float4* G4 = (const float4*)(g_bufA + (size_t)gbase * HID);
        #pragma unroll
        for (int i = 0; i < 8; i++) {
            int idx = tid + i * 1024;
            float4 vv = G4[idx];
            float d = DISF[idx >> 3];
            vv.x *= d; vv.y *= d; vv.z *= d; vv.w *= d;
            SG4w[idx] = vv;
        }
        if (tid < 32) SG[ZROW * HID + tid] = 0.f;
    }
    __syncthreads();

    float4 b1v = ((const float4*)b1)[c8];
    float w2[32];
    #pragma unroll
    for (int k = 0; k < 32; k++) w2[k] = W2t[k * 33 + lane];
    float* hrow = HROW + wid * 32;
    const unsigned short* __restrict__ srtb = g_srt + (size_t)h * HCAPP;
    for (int it = 0; it < 16; it++) {
        int ndl = wid * 16 + it;
        int ndg = (half << (shift - 1)) + ndl;
        int st = STARTs[ndl], m = DEGs[ndl];
        const unsigned short* srtp = srtb + st;
        unsigned long long acc01 = 0ull, acc23 = 0ull;
        if (grp4 == 0) {
            ulonglong2 s0 = *(const ulonglong2*)(SG + ndg * HID + (c8 << 2));
            acc01 = s0.x; acc23 = s0.y;
        }
        if (m > 0) {
            uint4 ev = *(const uint4*)(srtp + grp4 * 8);
            for (int p = 0; p < m; ) {
                uint4 evc = ev;
                p += 32;
                if (p < m) ev = *(const uint4*)(srtp + p + grp4 * 8);
                unsigned wd0 = evc.x, wd1 = evc.y, wd2 = evc.z, wd3 = evc.w;
                #pragma unroll
                for (int i = 0; i < 8; i++) {
                    unsigned wrd = (i < 2) ? wd0 : (i < 4) ? wd1 : (i < 6) ? wd2 : wd3;
                    int s = (i & 1) ? (int)(wrd >> 16) : (int)(wrd & 0xFFFFu);
                    ulonglong2 gg = *(const ulonglong2*)(SG + s * HID + (c8 << 2));
                    asm("add.rn.f32x2 %0, %0, %1;" : "+l"(acc01) : "l"(gg.x));
                    asm("add.rn.f32x2 %0, %0, %1;" : "+l"(acc23) : "l"(gg.y));
                }
            }
        }
        float ax = __uint_as_float((unsigned)acc01);
        float ay = __uint_as_float((unsigned)(acc01 >> 32));
        float az = __uint_as_float((unsigned)acc23);
        float aw = __uint_as_float((unsigned)(acc23 >> 32));
        ax += __shfl_xor_sync(FULL_MASK, ax, 8);
        ay += __shfl_xor_sync(FULL_MASK, ay, 8);
        az += __shfl_xor_sync(FULL_MASK, az, 8);
        aw += __shfl_xor_sync(FULL_MASK, aw, 8);
        ax += __shfl_xor_sync(FULL_MASK, ax, 16);
        ay += __shfl_xor_sync(FULL_MASK, ay, 16);
        az += __shfl_xor_sync(FULL_MASK, az, 16);
        aw += __shfl_xor_sync(FULL_MASK, aw, 16);
        if (grp4 == 0) {
            float d = DISF[ndg];
            float4 hh;
            hh.x = tanhf(fmaf(d, ax, b1v.x));
            hh.y = tanhf(fmaf(d, ay, b1v.y));
            hh.z = tanhf(fmaf(d, az, b1v.z));
            hh.w = tanhf(fmaf(d, aw, b1v.w));
            *(float4*)(hrow + (c8 << 2)) = hh;
        }
        __syncwarp();
        float a0 = 0.f, a1 = 0.f;
        #pragma unroll
        for (int k4 = 0; k4 < 8; k4++) {
            float4 hv = *(const float4*)(hrow + (k4 << 2));
            a0 += hv.x * w2[k4 * 4 + 0];
            a1 += hv.y * w2[k4 * 4 + 1];
            a0 += hv.z * w2[k4 * 4 + 2];
            a1 += hv.w * w2[k4 * 4 + 3];
        }
        __syncwarp();
        g_bufB[(size_t)(gbase + ndg) * HID + lane] = a0 + a1;
    }
}

// ---------------------------------------------------------------------------
// conv2: same gather; node linear via smem h-row; pool
__global__ void __launch_bounds__(1024, 1) k_conv2(const float* __restrict__ b2,
                                                   const float* __restrict__ Wl,
                                                   const float* __restrict__ bl,
                                                   int shift) {
    extern __shared__ char sm[];
    float*  SG     = (float*)sm;
    float*  DISF   = (float*)(sm + ODIS);
    int*    STARTs = (int*)(sm + OSTART);
    int*    DEGs   = (int*)(sm + ODEG);
    float*  Wlt    = (float*)(sm + OWT);
    float*  HROW   = (float*)(sm + OHROW);
    float*  POOL   = (float*)(sm + OPOOL);

    const int h     = blockIdx.x;
    const int half  = h & 1;
    const int gbase = (h >> 1) << shift;
    const int tid   = threadIdx.x;
    const int lane  = tid & 31;
    const int wid   = tid >> 5;
    const int c8    = lane & 7;
    const int grp4  = lane >> 3;
    const int node0 = gbase + (half << (shift - 1));

    DISF[tid] = g_dis[gbase + tid];
    if (tid < 512) {
        STARTs[tid] = g_start[node0 + tid];
        DEGs[tid]   = g_deg[node0 + tid];
    }
    {
        int r = tid >> 5, cc = tid & 31;
        Wlt[cc * 33 + r] = Wl[tid];
    }
    __syncthreads();
    {
        float4* SG4w = (float4*)SG;
        const float4* G4 = (const float4*)(g_bufB + (size_t)gbase * HID);
        #pragma unroll
        for (int i = 0; i < 8; i++) {
            int idx = tid + i * 1024;
            float4 vv = G4[idx];
            float d = DISF[idx >> 3];
            vv.x *= d; vv.y *= d; vv.z *= d; vv.w *= d;
            SG4w[idx] = vv;
        }
        if (tid < 32) SG[ZROW * HID + tid] = 0.f;
    }
    __syncthreads();

    float4 b2v = ((const float4*)b2)[c8];
    float wl[32];
    #pragma unroll
    for (int k = 0; k < 32; k++) wl[k] = Wlt[k * 33 + lane];
    float bll = bl[lane];
    float pacc = 0.f;
    float* hrow = HROW + wid * 32;
    const unsigned short* __restrict__ srtb = g_srt + (size_t)h * HCAPP;
    for (int it = 0; it < 16; it++) {
        int ndl = wid * 16 + it;
        int ndg = (half << (shift - 1)) + ndl;
        int st = STARTs[ndl], m = DEGs[ndl];
        const unsigned short* srtp = srtb + st;
        unsigned long long acc01 = 0ull, acc23 = 0ull;
        if (grp4 == 0) {
            ulonglong2 s0 = *(const ulonglong2*)(SG + ndg * HID + (c8 << 2));
            acc01 = s0.x; acc23 = s0.y;
        }
        if (m > 0) {
            uint4 ev = *(const uint4*)(srtp + grp4 * 8);
            for (int p = 0; p < m; ) {
                uint4 evc = ev;
                p += 32;
                if (p < m) ev = *(const uint4*)(srtp + p + grp4 * 8);
                unsigned wd0 = evc.x, wd1 = evc.y, wd2 = evc.z, wd3 = evc.w;
                #pragma unroll
                for (int i = 0; i < 8; i++) {
                    unsigned wrd = (i < 2) ? wd0 : (i < 4) ? wd1 : (i < 6) ? wd2 : wd3;
                    int s = (i & 1) ? (int)(wrd >> 16) : (int)(wrd & 0xFFFFu);
                    ulonglong2 gg = *(const ulonglong2*)(SG + s * HID + (c8 << 2));
                    asm("add.rn.f32x2 %0, %0, %1;" : "+l"(acc01) : "l"(gg.x));
                    asm("add.rn.f32x2 %0, %0, %1;" : "+l"(acc23) : "l"(gg.y));
                }
            }
        }
        float ax = __uint_as_float((unsigned)acc01);
        float ay = __uint_as_float((unsigned)(acc01 >> 32));
        float az = __uint_as_float((unsigned)acc23);
        float aw = __uint_as_float((unsigned)(acc23 >> 32));
        ax += __shfl_xor_sync(FULL_MASK, ax, 8);
        ay += __shfl_xor_sync(FULL_MASK, ay, 8);
        az += __shfl_xor_sync(FULL_MASK, az, 8);
        aw += __shfl_xor_sync(FULL_MASK, aw, 8);
        ax += __shfl_xor_sync(FULL_MASK, ax, 16);
        ay += __shfl_xor_sync(FULL_MASK, ay, 16);
        az += __shfl_xor_sync(FULL_MASK, az, 16);
        aw += __shfl_xor_sync(FULL_MASK, aw, 16);
        if (grp4 == 0) {
            float d = DISF[ndg];
            float4 hh;
            hh.x = tanhf(fmaf(d, ax, b2v.x));
            hh.y = tanhf(fmaf(d, ay, b2v.y));
            hh.z = tanhf(fmaf(d, az, b2v.z));
            hh.w = tanhf(fmaf(d, aw, b2v.w));
            *(float4*)(hrow + (c8 << 2)) = hh;
        }
        __syncwarp();
        float a0 = bll, a1 = 0.f;
        #pragma unroll
        for (int k4 = 0; k4 < 8; k4++) {
            float4 hv = *(const float4*)(hrow + (k4 << 2));
            a0 += hv.x * wl[k4 * 4 + 0];
            a1 += hv.y * wl[k4 * 4 + 1];
            a0 += hv.z * wl[k4 * 4 + 2];
            a1 += hv.w * wl[k4 * 4 + 3];
        }
        __syncwarp();
        pacc += tanhf(a0 + a1);
    }
    POOL[wid * 32 + lane] = pacc;
    __syncthreads();
    if (wid == 0) {
        float s = 0.f;
        #pragma unroll
        for (int w = 0; w < 32; w++) s += POOL[w * 32 + lane];
        g_pooled2[h * HID + lane] = s;
    }
}

// ---------------------------------------------------------------------------
__global__ void __launch_bounds__(1024) k_head(const float* __restrict__ share,
                        const float* __restrict__ Wp,  const float* __restrict__ bp,
                        const float* __restrict__ Vw1, const float* __restrict__ Vb1,
                        const float* __restrict__ Vw2, const float* __restrict__ Vb2,
                        const float* __restrict__ Vw3, const float* __restrict__ Vb3,
                        const float* __restrict__ Cw1, const float* __restrict__ Cb1,
                        const float* __restrict__ Cw2, const float* __restrict__ Cb2,
                        float* __restrict__ out, int nb) {
    __shared__ float Wpt[32 * 33], Vw1t[64 * 33], Vw2t[32 * 33],
                     Vw3t[32 * 33], Cw1t[64 * 33];
    int tid = threadIdx.x;
    int lane = tid & 31, wid = tid >> 5;
    {
        int r = tid >> 5, c = tid & 31;
        Wpt[c * 33 + r]  = Wp[tid];
        Vw2t[c * 33 + r] = Vw2[tid];
        Vw3t[c * 33 + r] = Vw3[tid];
    }
    for (int t = tid; t < 2048; t += 1024) {
        int r = t >> 6, c = t & 63;
        Vw1t[c * 33 + r] = Vw1[t];
        Cw1t[c * 33 + r] = Cw1[t];
    }
    __syncthreads();

    int b = blockIdx.x * 32 + wid;
    if (b >= nb) return;
    float pv = g_pooled2[(2 * b) * HID + lane] + g_pooled2[(2 * b + 1) * HID + lane];
    float h1 = bp[lane];
    #pragma unroll
    for (int k = 0; k < 32; k++) h1 += __shfl_sync(FULL_MASK, pv, k) * Wpt[k * 33 + lane];
    float s0 = share[b * 64 + lane];
    float s1 = share[b * 64 + 32 + lane];
    float t = Vb1[lane];
    #pragma unroll
    for (int k = 0; k < 32; k++) t += __shfl_sync(FULL_MASK, s0, k) * Vw1t[k * 33 + lane];
    #pragma unroll
    for (int k = 0; k < 32; k++) t += __shfl_sync(FULL_MASK, s1, k) * Vw1t[(k + 32) * 33 + lane];
    t = tanhf(t);
    float t2 = Vb2[lane];
    #pragma unroll
    for (int k = 0; k < 32; k++) t2 += __shfl_sync(FULL_MASK, t, k) * Vw2t[k * 33 + lane];
    t2 = tanhf(t2);
    float t3 = Vb3[lane];
    #pragma unroll
    for (int k = 0; k < 32; k++) t3 += __shfl_sync(FULL_MASK, t2, k) * Vw3t[k * 33 + lane];
    float z = Cb1[lane];
    #pragma unroll
    for (int k = 0; k < 32; k++) z += __shfl_sync(FULL_MASK, h1, k) * Cw1t[k * 33 + lane];
    #pragma unroll
    for (int k = 0; k < 32; k++) z += __shfl_sync(FULL_MASK, t3, k) * Cw1t[(k + 32) * 33 + lane];
    z = tanhf(z);
    float p = z * Cw2[lane];
    #pragma unroll
    for (int o = 16; o > 0; o >>= 1) p += __shfl_down_sync(FULL_MASK, p, o);
    if (lane == 0) out[b] = p + Cb2[0];
}

// ---------------------------------------------------------------------------
extern "C" void kernel_launch(void* const* d_in, const int* in_sizes, int n_in,
                              void* d_out, int out_size) {
    const float* x      = (const float*)d_in[0];
    const int*   edge   = (const int*)  d_in[1];
    const float* share  = (const float*)d_in[3];
    const float* W1 = (const float*)d_in[4];   const float* b1 = (const float*)d_in[5];
    const float* W2 = (const float*)d_in[6];   const float* b2 = (const float*)d_in[7];
    const float* Wl = (const float*)d_in[8];   const float* bl = (const float*)d_in[9];
    const float* Wp = (const float*)d_in[10];  const float* bp = (const float*)d_in[11];
    const float* Vw1 = (const float*)d_in[12]; const float* Vb1 = (const float*)d_in[13];
    const float* Vw2 = (const float*)d_in[14]; const float* Vb2 = (const float*)d_in[15];
    const float* Vw3 = (const float*)d_in[16]; const float* Vb3 = (const float*)d_in[17];
    const float* Cw1 = (const float*)d_in[18]; const float* Cb1 = (const float*)d_in[19];
    const float* Cw2 = (const float*)d_in[20]; const float* Cb2 = (const float*)d_in[21];

    const int n  = in_sizes[0] / 16;
    const int e  = in_sizes[1] / 2;
    const int nb = in_sizes[3] / 64;
    const int* src = edge;
    const int* dst = edge + e;
    float* out = (float*)d_out;

    int pp = n / nb;                     // 1024
    int shift = 0;
    while ((1 << shift) < pp) shift++;
    const int nh = nb * 2;

    const int SM_SORT  = 2048 + 64 + 2 * HCAP + 2 * HCAPP + 16 * 33 * 4;
    const int SM_CONV1 = OPOOL;                // conv1 doesn't use POOL
    const int SM_CONV2 = OPOOL + 4096;
    static int smem_set = 0;
    if (!smem_set) {
        cudaFuncSetAttribute(k_sort,  cudaFuncAttributeMaxDynamicSharedMemorySize, SM_SORT);
        cudaFuncSetAttribute(k_conv1, cudaFuncAttributeMaxDynamicSharedMemorySize, SM_CONV1);
        cudaFuncSetAttribute(k_conv2, cudaFuncAttributeMaxDynamicSharedMemorySize, SM_CONV2);
        smem_set = 1;
    }

    k_init0<<<1, 128>>>();
    k_group<<<(e + CHUNK - 1) / CHUNK, 512>>>(src, dst, e, shift);
    k_sort<<<nh, 512, SM_SORT>>>(x, W1, shift);
    k_conv1<<<nh, 1024, SM_CONV1>>>(b1, W2, shift);
    k_conv2<<<nh, 1024, SM_CONV2>>>(b2, Wl, bl, shift);
    k_head<<<(nb + 31) / 32, 1024>>>(share, Wp, bp, Vw1, Vb1, Vw2, Vb2, Vw3, Vb3,
                                     Cw1, Cb1, Cw2, Cb2, out, nb);
}